// round 6
// baseline (speedup 1.0000x reference)
#include <cuda_runtime.h>
#include <cuda_bf16.h>
#include <cstdint>

#define S_LEN 2048
#define B_SZ  2
#define D_MOD 1024
#define H_NUM 16
#define DH_SZ 64
#define WIN_SZ 256
#define M_ROWS (S_LEN * B_SZ)   // 4096

// Scratch (device globals — no allocation allowed)
__device__ float g_swa_Q[M_ROWS * D_MOD];
__device__ float g_swa_K[M_ROWS * D_MOD];
__device__ float g_swa_V[M_ROWS * D_MOD];
__device__ float g_swa_O[M_ROWS * D_MOD];
__device__ float g_swa_XC[M_ROWS * D_MOD];       // tf32-rounded x
__device__ float g_swa_WT[4 * D_MOD * D_MOD];    // tf32-rounded W^T (q,k,v,o), [n][k]

// ---------------------------------------------------------------------------
__device__ __forceinline__ uint32_t f2tf32(float x) {
    uint32_t r;
    asm("cvt.rna.tf32.f32 %0, %1;" : "=r"(r) : "f"(x));
    return r;
}
__device__ __forceinline__ float tf32f(float x) { return __uint_as_float(f2tf32(x)); }

__device__ __forceinline__ void cp16(uint32_t dst_smem, const void* src) {
    asm volatile("cp.async.cg.shared.global [%0], [%1], 16;"
                 :: "r"(dst_smem), "l"(src));
}

__device__ __forceinline__ void ldsm4(uint32_t& r0, uint32_t& r1, uint32_t& r2,
                                      uint32_t& r3, uint32_t addr) {
    asm volatile("ldmatrix.sync.aligned.m8n8.x4.shared.b16 {%0,%1,%2,%3}, [%4];"
                 : "=r"(r0), "=r"(r1), "=r"(r2), "=r"(r3) : "r"(addr));
}

__device__ __forceinline__ void mma_tf32(float c[4], const uint32_t a[4],
                                         const uint32_t b0, const uint32_t b1) {
    asm volatile(
        "mma.sync.aligned.m16n8k8.row.col.f32.tf32.tf32.f32 "
        "{%0,%1,%2,%3}, {%4,%5,%6,%7}, {%8,%9}, {%0,%1,%2,%3};"
        : "+f"(c[0]), "+f"(c[1]), "+f"(c[2]), "+f"(c[3])
        : "r"(a[0]), "r"(a[1]), "r"(a[2]), "r"(a[3]), "r"(b0), "r"(b1));
}

// ---------------------------------------------------------------------------
// pre-pass: tf32-round x; transpose+round W -> WT[n][k]
// ---------------------------------------------------------------------------
__global__ void swa_prep_x(const float4* __restrict__ x, float4* __restrict__ xc) {
    const int i = blockIdx.x * 256 + threadIdx.x;
    float4 v = x[i];
    v.x = tf32f(v.x); v.y = tf32f(v.y); v.z = tf32f(v.z); v.w = tf32f(v.w);
    xc[i] = v;
}

__global__ void swa_prep_wt(const float* __restrict__ Wq, const float* __restrict__ Wk,
                            const float* __restrict__ Wv, const float* __restrict__ Wo,
                            float* __restrict__ WT) {
    __shared__ float t[32][33];
    const float* W = (blockIdx.z == 0) ? Wq : (blockIdx.z == 1) ? Wk
                   : (blockIdx.z == 2) ? Wv : Wo;
    float* Dst = WT + (size_t)blockIdx.z * D_MOD * D_MOD;
    const int n0 = blockIdx.x * 32, k0 = blockIdx.y * 32;
#pragma unroll
    for (int i = threadIdx.y; i < 32; i += 8)
        t[i][threadIdx.x] = tf32f(W[(size_t)(k0 + i) * D_MOD + n0 + threadIdx.x]);
    __syncthreads();
#pragma unroll
    for (int i = threadIdx.y; i < 32; i += 8)
        Dst[(size_t)(n0 + i) * D_MOD + k0 + threadIdx.x] = t[threadIdx.x][i];
}

// ---------------------------------------------------------------------------
// tf32 mma.sync GEMM v3: 128x128x32 tiles, 128 threads (4 warps, 64x64 warp
// tiles), ldmatrix fragments, cp.async double buffer, 2 CTAs/SM.
// C = A[m][k] @ WT[n][k]^T + bias ; ROUND -> tf32-round the output store.
// smem (bytes): As0@0  As1@18432  Bs0@36864  Bs1@55296  (pitch 36 floats)
// ---------------------------------------------------------------------------
#define GPITCH 36
#define GEMM_SMEM 73728

template <bool ROUND>
__device__ __forceinline__
void gemm_body(const float* __restrict__ A, const float* __restrict__ B,
               const float* __restrict__ bias, float* __restrict__ C) {
    extern __shared__ float sm[];
    const uint32_t smb = (uint32_t)__cvta_generic_to_shared(sm);
    const int tid  = threadIdx.x;
    const int lane = tid & 31;
    const int warp = tid >> 5;
    const int wr   = warp & 1;          // m: 0..1 -> 64*wr
    const int wc   = warp >> 1;         // n: 0..1 -> 64*wc
    const int m0   = blockIdx.y * 128;
    const int n0   = blockIdx.x * 128;

    const float* Ab = A + (size_t)m0 * 1024;
    const float* Bb = B + (size_t)n0 * 1024;

    // ldmatrix per-lane offsets (bytes), pitch = 144 B
    const int mi = lane >> 3, rr = lane & 7;
    uint32_t aOff[4], bOff[4];
#pragma unroll
    for (int mt = 0; mt < 4; ++mt) {
        const int row = wr * 64 + mt * 16 + (mi & 1) * 8 + rr;
        aOff[mt] = (uint32_t)(row * GPITCH + (mi >> 1) * 4) * 4;
    }
#pragma unroll
    for (int p = 0; p < 4; ++p) {
        const int row = wc * 64 + p * 16 + (mi >> 1) * 8 + rr;
        bOff[p] = (uint32_t)(row * GPITCH + (mi & 1) * 4) * 4;
    }

    float acc[4][8][4];
#pragma unroll
    for (int mt = 0; mt < 4; ++mt)
#pragma unroll
        for (int nt = 0; nt < 8; ++nt)
#pragma unroll
            for (int i = 0; i < 4; ++i) acc[mt][nt][i] = 0.0f;

    auto stage = [&](int kc) {
        const uint32_t as = smb + ((kc & 1) ? 18432u : 0u);
        const uint32_t bs = smb + ((kc & 1) ? 55296u : 36864u);
        const int k0 = kc * 32;
#pragma unroll
        for (int i = 0; i < 8; ++i) {
            const int idx = tid + i * 128;
            const int r = idx >> 3, f4 = idx & 7;
            cp16(as + (uint32_t)(r * 144 + f4 * 16), Ab + (size_t)r * 1024 + k0 + f4 * 4);
            cp16(bs + (uint32_t)(r * 144 + f4 * 16), Bb + (size_t)r * 1024 + k0 + f4 * 4);
        }
    };

    stage(0);
    asm volatile("cp.async.commit_group;");

    const int NIT = 1024 / 32;
    for (int kc = 0; kc < NIT; ++kc) {
        if (kc + 1 < NIT) {
            stage(kc + 1);
            asm volatile("cp.async.commit_group;");
            asm volatile("cp.async.wait_group 1;");
        } else {
            asm volatile("cp.async.wait_group 0;");
        }
        __syncthreads();

        const uint32_t as = smb + ((kc & 1) ? 18432u : 0u);
        const uint32_t bs = smb + ((kc & 1) ? 55296u : 36864u);
#pragma unroll
        for (int ks = 0; ks < 4; ++ks) {
            const uint32_t kb = (uint32_t)(ks * 8 * 4);
            uint32_t af[4][4], bf[4][4];
#pragma unroll
            for (int mt = 0; mt < 4; ++mt)
                ldsm4(af[mt][0], af[mt][1], af[mt][2], af[mt][3], as + aOff[mt] + kb);
#pragma unroll
            for (int p = 0; p < 4; ++p)
                ldsm4(bf[p][0], bf[p][1], bf[p][2], bf[p][3], bs + bOff[p] + kb);
#pragma unroll
            for (int mt = 0; mt < 4; ++mt)
#pragma unroll
                for (int p = 0; p < 4; ++p) {
                    mma_tf32(acc[mt][2 * p + 0], af[mt], bf[p][0], bf[p][1]);
                    mma_tf32(acc[mt][2 * p + 1], af[mt], bf[p][2], bf[p][3]);
                }
        }
        __syncthreads();
    }

    // epilogue
#pragma unroll
    for (int mt = 0; mt < 4; ++mt) {
        const int row = m0 + wr * 64 + mt * 16 + (lane >> 2);
#pragma unroll
        for (int nt = 0; nt < 8; ++nt) {
            const int col = n0 + wc * 64 + nt * 8 + 2 * (lane & 3);
            const float2 bia = *(const float2*)&bias[col];
            float2 o0, o1;
            o0.x = acc[mt][nt][0] + bia.x;
            o0.y = acc[mt][nt][1] + bia.y;
            o1.x = acc[mt][nt][2] + bia.x;
            o1.y = acc[mt][nt][3] + bia.y;
            if (ROUND) {
                o0.x = tf32f(o0.x); o0.y = tf32f(o0.y);
                o1.x = tf32f(o1.x); o1.y = tf32f(o1.y);
            }
            *(float2*)&C[(size_t)row * 1024 + col] = o0;
            *(float2*)&C[(size_t)(row + 8) * 1024 + col] = o1;
        }
    }
}

__global__ __launch_bounds__(128, 2)
void swa_gemm_qkv(const float* __restrict__ xc, const float* __restrict__ WT,
                  const float* __restrict__ bq, const float* __restrict__ bk,
                  const float* __restrict__ bv,
                  float* __restrict__ Q, float* __restrict__ K, float* __restrict__ V) {
    const int z = blockIdx.z;
    const float* W = WT + (size_t)z * D_MOD * D_MOD;
    const float* bias = (z == 0) ? bq : (z == 1) ? bk : bv;
    float* C = (z == 0) ? Q : (z == 1) ? K : V;
    gemm_body<true>(xc, W, bias, C);     // round: consumed by attention MMAs
}

__global__ __launch_bounds__(128, 2)
void swa_gemm_o(const float* __restrict__ A, const float* __restrict__ WT,
                const float* __restrict__ bias, float* __restrict__ C) {
    gemm_body<false>(A, WT + (size_t)3 * D_MOD * D_MOD, bias, C);
}

// ---------------------------------------------------------------------------
// Attention: tf32 mma QK^T and P@V, register online softmax.
// K/V arrive pre-rounded to tf32 (QKV epilogue) -> no cvt at staging.
// ---------------------------------------------------------------------------
#define AQ_OFF 0
#define AK_OFF 4352
#define AP_OFF 8704
#define AV_OFF 13056
#define ATTN_SMEM_BYTES (17664 * 4)

__global__ __launch_bounds__(128, 3)
void swa_attn3(const float* __restrict__ Q, const float* __restrict__ K,
               const float* __restrict__ V, const float* __restrict__ beta,
               float* __restrict__ O) {
    extern __shared__ float smf[];
    float* Qs = smf + AQ_OFF;
    float* Ks = smf + AK_OFF;
    float* Ps = smf + AP_OFF;
    float* Vs = smf + AV_OFF;

    const int z  = blockIdx.y;
    const int b  = z / H_NUM;
    const int h  = z % H_NUM;
    const int q0 = blockIdx.x * 64;
    const int tid  = threadIdx.x;
    const int lane = tid & 31;
    const int warp = tid >> 5;
    const int g  = lane >> 2;
    const int t4 = lane & 3;

    const float scale = 1.0f / (8.0f * __expf(beta[h]));

#pragma unroll
    for (int it = 0; it < 8; ++it) {
        const int f = tid + it * 128;
        const int row = f >> 4, c4 = f & 15;
        float4 v = *(const float4*)&Q[((size_t)((q0 + row) * B_SZ + b)) * D_MOD + h * DH_SZ + c4 * 4];
        float4 w;
        w.x = tf32f(v.x * scale); w.y = tf32f(v.y * scale);
        w.z = tf32f(v.z * scale); w.w = tf32f(v.w * scale);
        *(float4*)&Qs[row * 68 + c4 * 4] = w;
    }
    __syncthreads();

    uint32_t qa[8][4];
    const int r0 = 16 * warp + g;
#pragma unroll
    for (int kk = 0; kk < 8; ++kk) {
        qa[kk][0] = __float_as_uint(Qs[r0 * 68 + kk * 8 + t4]);
        qa[kk][1] = __float_as_uint(Qs[(r0 + 8) * 68 + kk * 8 + t4]);
        qa[kk][2] = __float_as_uint(Qs[r0 * 68 + kk * 8 + t4 + 4]);
        qa[kk][3] = __float_as_uint(Qs[(r0 + 8) * 68 + kk * 8 + t4 + 4]);
    }

    float acc[8][4];
#pragma unroll
    for (int j = 0; j < 8; ++j)
#pragma unroll
        for (int i = 0; i < 4; ++i) acc[j][i] = 0.0f;

    float m0 = 0.0f, m1 = 0.0f, l0 = 1.0f, l1 = 1.0f;
    const int qr0 = q0 + r0;
    const int qr1 = qr0 + 8;

    int kbeg = q0 - (WIN_SZ - 1);
    if (kbeg < 0) kbeg = 0;
    kbeg &= ~63;

    for (int t = kbeg; t < q0 + 64; t += 64) {
        // stage K/V (already tf32-rounded, raw copy)
#pragma unroll
        for (int it = 0; it < 8; ++it) {
            const int f = tid + it * 128;
            const int kk = f >> 4, d4 = f & 15;
            const size_t gofs = ((size_t)((t + kk) * B_SZ + b)) * D_MOD + h * DH_SZ + d4 * 4;
            *(float4*)&Ks[kk * 68 + d4 * 4] = *(const float4*)&K[gofs];
            *(float4*)&Vs[kk * 72 + d4 * 4] = *(const float4*)&V[gofs];
        }
        __syncthreads();

        float c[8][4];
#pragma unroll
        for (int j = 0; j < 8; ++j)
#pragma unroll
            for (int i = 0; i < 4; ++i) c[j][i] = 0.0f;

#pragma unroll
        for (int kk = 0; kk < 8; ++kk) {
#pragma unroll
            for (int j = 0; j < 8; ++j) {
                const uint32_t b0 = __float_as_uint(Ks[(j * 8 + g) * 68 + kk * 8 + t4]);
                const uint32_t b1 = __float_as_uint(Ks[(j * 8 + g) * 68 + kk * 8 + t4 + 4]);
                mma_tf32(c[j], qa[kk], b0, b1);
            }
        }

#pragma unroll
        for (int j = 0; j < 8; ++j) {
            const int k0i = t + j * 8 + 2 * t4;
#pragma unroll
            for (int u = 0; u < 2; ++u) {
                const int kidx = k0i + u;
                const int d0 = qr0 - kidx;
                const int d1 = qr1 - kidx;
                if (!(d0 >= 0 && d0 < WIN_SZ)) c[j][u] = -1e30f;
                if (!(d1 >= 0 && d1 < WIN_SZ)) c[j][2 + u] = -1e30f;
            }
        }

        float mx0 = m0, mx1 = m1;
#pragma unroll
        for (int j = 0; j < 8; ++j) {
            mx0 = fmaxf(mx0, fmaxf(c[j][0], c[j][1]));
            mx1 = fmaxf(mx1, fmaxf(c[j][2], c[j][3]));
        }
        mx0 = fmaxf(mx0, __shfl_xor_sync(0xffffffffu, mx0, 1));
        mx0 = fmaxf(mx0, __shfl_xor_sync(0xffffffffu, mx0, 2));
        mx1 = fmaxf(mx1, __shfl_xor_sync(0xffffffffu, mx1, 1));
        mx1 = fmaxf(mx1, __shfl_xor_sync(0xffffffffu, mx1, 2));

        const float fs0 = __expf(m0 - mx0);
        const float fs1 = __expf(m1 - mx1);
        float s0 = 0.0f, s1 = 0.0f;
#pragma unroll
        for (int j = 0; j < 8; ++j) {
            const float p0 = __expf(c[j][0] - mx0);
            const float p1 = __expf(c[j][1] - mx0);
            const float p2 = __expf(c[j][2] - mx1);
            const float p3 = __expf(c[j][3] - mx1);
            s0 += p0 + p1;
            s1 += p2 + p3;
            float2 w0, w1;
            w0.x = tf32f(p0); w0.y = tf32f(p1);
            w1.x = tf32f(p2); w1.y = tf32f(p3);
            *(float2*)&Ps[r0 * 68 + j * 8 + 2 * t4] = w0;
            *(float2*)&Ps[(r0 + 8) * 68 + j * 8 + 2 * t4] = w1;
        }
        s0 += __shfl_xor_sync(0xffffffffu, s0, 1);
        s0 += __shfl_xor_sync(0xffffffffu, s0, 2);
        s1 += __shfl_xor_sync(0xffffffffu, s1, 1);
        s1 += __shfl_xor_sync(0xffffffffu, s1, 2);

        l0 = l0 * fs0 + s0;
        l1 = l1 * fs1 + s1;
        m0 = mx0; m1 = mx1;

#pragma unroll
        for (int j = 0; j < 8; ++j) {
            acc[j][0] *= fs0; acc[j][1] *= fs0;
            acc[j][2] *= fs1; acc[j][3] *= fs1;
        }
        __syncwarp();

#pragma unroll
        for (int kk = 0; kk < 8; ++kk) {
            uint32_t pa[4];
            pa[0] = __float_as_uint(Ps[r0 * 68 + kk * 8 + t4]);
            pa[1] = __float_as_uint(Ps[(r0 + 8) * 68 + kk * 8 + t4]);
            pa[2] = __float_as_uint(Ps[r0 * 68 + kk * 8 + t4 + 4]);
            pa[3] = __float_as_uint(Ps[(r0 + 8) * 68 + kk * 8 + t4 + 4]);
#pragma unroll
            for (int j = 0; j < 8; ++j) {
                const uint32_t v0 = __float_as_uint(Vs[(kk * 8 + t4) * 72 + j * 8 + g]);
                const uint32_t v1 = __float_as_uint(Vs[(kk * 8 + t4 + 4) * 72 + j * 8 + g]);
                mma_tf32(acc[j], pa, v0, v1);
            }
        }
        __syncthreads();
    }

    // normalize + store (tf32-rounded so the O-GEMM stages raw)
    const float rl0 = 1.0f / l0;
    const float rl1 = 1.0f / l1;
#pragma unroll
    for (int j = 0; j < 8; ++j) {
        const int col = h * DH_SZ + j * 8 + 2 * t4;
        float2 o0, o1;
        o0.x = tf32f(acc[j][0] * rl0); o0.y = tf32f(acc[j][1] * rl0);
        o1.x = tf32f(acc[j][2] * rl1); o1.y = tf32f(acc[j][3] * rl1);
        *(float2*)&O[((size_t)(qr0 * B_SZ + b)) * D_MOD + col] = o0;
        *(float2*)&O[((size_t)(qr1 * B_SZ + b)) * D_MOD + col] = o1;
    }
}

// ---------------------------------------------------------------------------
extern "C" void kernel_launch(void* const* d_in, const int* in_sizes, int n_in,
                              void* d_out, int out_size) {
    const float* x    = (const float*)d_in[0];
    const float* beta = (const float*)d_in[1];
    const float* Wq   = (const float*)d_in[2];
    const float* bq   = (const float*)d_in[3];
    const float* Wk   = (const float*)d_in[4];
    const float* bk   = (const float*)d_in[5];
    const float* Wv   = (const float*)d_in[6];
    const float* bv   = (const float*)d_in[7];
    const float* Wo   = (const float*)d_in[8];
    const float* bo   = (const float*)d_in[9];
    float* out = (float*)d_out;

    float *Qp, *Kp, *Vp, *Op, *XCp, *WTp;
    cudaGetSymbolAddress((void**)&Qp,  g_swa_Q);
    cudaGetSymbolAddress((void**)&Kp,  g_swa_K);
    cudaGetSymbolAddress((void**)&Vp,  g_swa_V);
    cudaGetSymbolAddress((void**)&Op,  g_swa_O);
    cudaGetSymbolAddress((void**)&XCp, g_swa_XC);
    cudaGetSymbolAddress((void**)&WTp, g_swa_WT);

    cudaFuncSetAttribute(swa_attn3, cudaFuncAttributeMaxDynamicSharedMemorySize,
                         ATTN_SMEM_BYTES);
    cudaFuncSetAttribute(swa_gemm_qkv, cudaFuncAttributeMaxDynamicSharedMemorySize,
                         GEMM_SMEM);
    cudaFuncSetAttribute(swa_gemm_o, cudaFuncAttributeMaxDynamicSharedMemorySize,
                         GEMM_SMEM);

    swa_prep_x<<<(M_ROWS * D_MOD / 4) / 256, 256>>>((const float4*)x, (float4*)XCp);
    swa_prep_wt<<<dim3(32, 32, 4), dim3(32, 8)>>>(Wq, Wk, Wv, Wo, WTp);

    dim3 qkvgrid(D_MOD / 128, M_ROWS / 128, 3);   // (8, 32, 3)
    swa_gemm_qkv<<<qkvgrid, 128, GEMM_SMEM>>>(XCp, WTp, bq, bk, bv, Qp, Kp, Vp);

    dim3 agrid(S_LEN / 64, B_SZ * H_NUM);         // (32, 32)
    swa_attn3<<<agrid, 128, ATTN_SMEM_BYTES>>>(Qp, Kp, Vp, beta, Op);

    dim3 ogrid(D_MOD / 128, M_ROWS / 128);        // (8, 32)
    swa_gemm_o<<<ogrid, 128, GEMM_SMEM>>>(Op, WTp, bo, out);
}